// round 2
// baseline (speedup 1.0000x reference)
#include <cuda_runtime.h>

// Problem constants (fixed shapes for this problem instance)
#define BATCH   2
#define H       64
#define W       64
#define C       128
#define N_IN    (H * W * C)            // 524288
#define N_POOL  ((H/2) * (W/2) * C)    // 131072
#define N_OUT   32

// Output layout (concatenation of the 4 reference outputs, all float32):
//   [0, OFF1)          w_zero #1 : BATCH * N_IN * N_OUT = 33,554,432
//   [OFF1, OFF2)       b_out_u_  : BATCH * N_OUT        = 64
//   [OFF2, OFF3)       w_zero #2 : 33,554,432
//   [OFF3, TOTAL)      b_out_l_  : 64
#define OFF1    (BATCH * N_IN * N_OUT)         // 33554432
#define OFF2    (OFF1 + BATCH * N_OUT)         // 33554496
#define OFF3    (OFF2 + BATCH * N_IN * N_OUT)  // 67108928
#define TOTAL   (OFF3 + BATCH * N_OUT)         // 67108992
#define TOTAL4  (TOTAL / 4)                    // 16777248 float4s
#define SKIP_BEG (OFF1 / 4)                    // 8388608  (bias slot 1 in float4 units)
#define SKIP_END (OFF2 / 4)                    // 8388624
// bias slot 2 is exactly the tail [OFF3/4, TOTAL4) = [16777232, 16777248)
#define ZTAIL4   (OFF3 / 4)                    // 16777232

// Work split inside the fused kernel
#define ZBLOCKS  1792
#define RBLOCKS  512
#define NTHREADS 256
#define ROWS_TOTAL (BATCH * N_POOL)                  // 262144
#define ROWS_PER_WARP (ROWS_TOTAL / (RBLOCKS * 8))   // 64

// K1: seed the two bias slots with the input biases (so K2's atomicAdds
// accumulate onto correct initial values, not 0xAA poison).
__global__ void init_bias_kernel(float* __restrict__ out,
                                 const float* __restrict__ b_out_u,
                                 const float* __restrict__ b_out_l) {
    int i = threadIdx.x;           // 0..63  (= BATCH * N_OUT)
    if (i < BATCH * N_OUT) {
        out[OFF1 + i] = b_out_u[i];
        out[OFF3 + i] = b_out_l[i];
    }
}

// K2: fused zero-fill (blocks [0, ZBLOCKS)) + pool/reduce (blocks [ZBLOCKS, ZBLOCKS+RBLOCKS)).
// The two roles overlap store-bandwidth and load-bandwidth on HBM.
__global__ void __launch_bounds__(NTHREADS)
fused_kernel(float* __restrict__ out,
             const float* __restrict__ u_c,
             const float* __restrict__ l_c,
             const float* __restrict__ w_out_u,
             const float* __restrict__ w_out_l) {
    if (blockIdx.x < ZBLOCKS) {
        // ---- zero-fill role: float4 grid-stride over the two w_zero regions ----
        float4* o4 = reinterpret_cast<float4*>(out);
        const float4 z = make_float4(0.f, 0.f, 0.f, 0.f);
        const int stride = ZBLOCKS * NTHREADS;
        // region A: [0, SKIP_BEG) ∪ [SKIP_END, ZTAIL4)
        for (int i = blockIdx.x * NTHREADS + threadIdx.x; i < ZTAIL4; i += stride) {
            if (i >= SKIP_BEG && i < SKIP_END) continue;   // bias slot 1
            o4[i] = z;
        }
        return;
    }

    // ---- reduce role ----
    const int rb   = blockIdx.x - ZBLOCKS;
    const int warp = threadIdx.x >> 5;
    const int lane = threadIdx.x & 31;
    const int gw   = rb * 8 + warp;              // global warp id, 0..4095
    const int r0   = gw * ROWS_PER_WARP;         // first row for this warp
    const int b    = r0 >> 17;                   // batch (rows per batch = 131072, warp-aligned)

    float accu = 0.f;   // contribution to b_out_u_[b, lane]
    float accl = 0.f;   // contribution to b_out_l_[b, lane]

    #pragma unroll 4
    for (int i = 0; i < ROWS_PER_WARP; i++) {
        const int r = r0 + i;                    // global row (b * N_POOL + p)
        const int p = r & (N_POOL - 1);
        const int c  = p & 127;
        const int ow = (p >> 7) & 31;
        const int oh = p >> 12;
        // 2x2 maxpool window base in the (H,W,C) input for this batch
        const int base = b * N_IN + oh * (2 * W * C) + ow * (2 * C) + c;

        // fused pool: recompute max bounds directly (broadcast loads, 1 line each)
        const float u0 = __ldg(u_c + base);
        const float u1 = __ldg(u_c + base + C);
        const float u2 = __ldg(u_c + base + W * C);
        const float u3 = __ldg(u_c + base + W * C + C);
        const float bu = fmaxf(fmaxf(u0, u1), fmaxf(u2, u3));

        const float l0 = __ldg(l_c + base);
        const float l1 = __ldg(l_c + base + C);
        const float l2 = __ldg(l_c + base + W * C);
        const float l3 = __ldg(l_c + base + W * C + C);
        const float bl = fmaxf(fmaxf(l0, l1), fmaxf(l2, l3));

        // coalesced weight rows: lane = output index o
        const float wu = __ldg(w_out_u + r * N_OUT + lane);
        const float wl = __ldg(w_out_l + r * N_OUT + lane);

        accu += fmaxf(wu, 0.f) * bu + fminf(wu, 0.f) * bl;
        accl += fmaxf(wl, 0.f) * bl + fminf(wl, 0.f) * bu;
    }

    // block reduction across the 8 warps (all same batch b: 512 rows/block,
    // batch boundary at row 131072 is block-aligned)
    __shared__ float su[8][32];
    __shared__ float sl[8][32];
    su[warp][lane] = accu;
    sl[warp][lane] = accl;
    __syncthreads();

    if (warp == 0) {
        float s = 0.f;
        #pragma unroll
        for (int k = 0; k < 8; k++) s += su[k][lane];
        atomicAdd(&out[OFF1 + b * N_OUT + lane], s);
    } else if (warp == 1) {
        float s = 0.f;
        #pragma unroll
        for (int k = 0; k < 8; k++) s += sl[k][lane];
        atomicAdd(&out[OFF3 + b * N_OUT + lane], s);
    }
}

extern "C" void kernel_launch(void* const* d_in, const int* in_sizes, int n_in,
                              void* d_out, int out_size) {
    // metadata order: y, x_0, u_c, l_c, w_out_u, b_out_u, w_out_l, b_out_l
    const float* u_c     = (const float*)d_in[2];
    const float* l_c     = (const float*)d_in[3];
    const float* w_out_u = (const float*)d_in[4];
    const float* b_out_u = (const float*)d_in[5];
    const float* w_out_l = (const float*)d_in[6];
    const float* b_out_l = (const float*)d_in[7];
    float* out = (float*)d_out;

    init_bias_kernel<<<1, 64>>>(out, b_out_u, b_out_l);
    fused_kernel<<<ZBLOCKS + RBLOCKS, NTHREADS>>>(out, u_c, l_c, w_out_u, w_out_l);
}